// round 11
// baseline (speedup 1.0000x reference)
#include <cuda_runtime.h>
#include <cstdint>

#define BATCH 64
#define NSPEC 8
#define VOCAB 128000
#define ROWS (BATCH * NSPEC)               // 512
#define VEC_PER_ROW (VOCAB / 4)            // 32000
#define UNITS_PER_ROW 25
#define VEC_PER_UNIT (VEC_PER_ROW / UNITS_PER_ROW)   // 1280
#define NUNITS (ROWS * UNITS_PER_ROW)      // 12800
#define NTHREADS 128
#define VPT 10                             // float4 per thread per unit (1280/128)
#define NWORKERS 1184                      // 148 SMs * 8 CTAs, persistent-style

// Scratch (device globals, allocation-free; zero-initialized at module load,
// re-zeroed by the epilogue each call -> graph-replay deterministic).
__device__ unsigned long long g_row[ROWS]; // packed (ford(val)<<32 | ~idx) max
__device__ unsigned g_ticket;
__device__ unsigned g_count;

// Monotone order-preserving fp32 -> u32 (no NaNs in input).
__device__ __forceinline__ unsigned ford(float f) {
    unsigned u = __float_as_uint(f);
    return u ^ ((unsigned)((int)u >> 31) | 0x80000000u);
}

__device__ __forceinline__ float max4(float4 v) {
    return fmaxf(fmaxf(v.x, v.y), fmaxf(v.z, v.w));
}

// Work-stealing persistent kernel: units of 1280 float4 pulled via ticket,
// per-warp argmax folded into g_row[row] with u64 atomicMax.
__global__ void __launch_bounds__(NTHREADS, 8)
fused_kernel(const float* __restrict__ logits,
             const void* __restrict__ draft_raw,
             const void* __restrict__ bonus_raw,
             float* __restrict__ out) {
    const float4* __restrict__ vec = reinterpret_cast<const float4*>(logits);
    __shared__ int s_last;
    __shared__ int s_not64;

    unsigned t = (threadIdx.x == 0) ? atomicAdd(&g_ticket, 1u) : 0u;
    t = __shfl_sync(0xFFFFFFFFu, t, 0);            // warp 0 lane0 value...
    // broadcast across CTA via shared
    __shared__ unsigned s_t;
    if (threadIdx.x == 0) s_t = t;
    __syncthreads();
    t = s_t;

    while (t < NUNITS) {
        const int row = t / UNITS_PER_ROW;
        const int seg = t - row * UNITS_PER_ROW;
        const int k0 = seg * VEC_PER_UNIT + threadIdx.x;   // vec idx in row
        const float4* __restrict__ pr = vec + (size_t)row * VEC_PER_ROW + k0;

        float4 v[VPT];
#pragma unroll
        for (int j = 0; j < VPT; ++j) v[j] = __ldcs(pr + j * NTHREADS);

        // Prefetch next ticket while loads are in flight.
        unsigned tn = (threadIdx.x == 0) ? atomicAdd(&g_ticket, 1u) : 0u;

        float m[VPT];
#pragma unroll
        for (int j = 0; j < VPT; ++j) m[j] = max4(v[j]);
        float bm = m[0];
#pragma unroll
        for (int j = 1; j < VPT; ++j) bm = fmaxf(bm, m[j]);

        // Exact within-row element index, earliest-first (jnp tie-break).
        int bidx = 0;
        bool f = false;
#pragma unroll
        for (int j = 0; j < VPT; ++j) {
            const int base = (k0 + j * NTHREADS) * 4;
            if (!f && v[j].x == bm) { bidx = base;     f = true; }
            if (!f && v[j].y == bm) { bidx = base + 1; f = true; }
            if (!f && v[j].z == bm) { bidx = base + 2; f = true; }
            if (!f && v[j].w == bm) { bidx = base + 3; f = true; }
        }

        unsigned long long key =
            ((unsigned long long)ford(bm) << 32) |
            (unsigned long long)(0xFFFFFFFFu - (unsigned)bidx);

#pragma unroll
        for (int off = 16; off > 0; off >>= 1) {
            unsigned long long o = __shfl_down_sync(0xFFFFFFFFu, key, off);
            key = (o > key) ? o : key;
        }
        if ((threadIdx.x & 31) == 0)
            atomicMax(&g_row[row], key);           // 4 atomics/unit, 512 addrs

        if (threadIdx.x == 0) s_t = tn;
        __syncthreads();
        t = s_t;
    }

    // ---- last-CTA-done handshake ----
    if (threadIdx.x == 0) {
        __threadfence();
        unsigned c = atomicAdd(&g_count, 1u);
        s_last = (c == (unsigned)(gridDim.x - 1));
        s_not64 = 0;
    }
    __syncthreads();
    if (!s_last) return;
    __threadfence();                               // acquire all atomicMax

    // ---- rejection-sampling epilogue ----
    // Runtime input dtype detect: first 2048 B of draft exist under either
    // dtype; int64 => every high word is 0 (tokens < 128000).
    const unsigned long long* d64chk = (const unsigned long long*)draft_raw;
    for (int j = threadIdx.x; j < 256; j += NTHREADS)
        if (d64chk[j] >> 32) atomicOr(&s_not64, 1);
    __syncthreads();
    const bool is64 = (s_not64 == 0);

    const int b = threadIdx.x;
    if (b < BATCH) {
        const long long* draft64 = (const long long*)draft_raw;
        const int*       draft32 = (const int*)draft_raw;
        const long long* bonus64 = (const long long*)bonus_raw;
        const int*       bonus32 = (const int*)bonus_raw;
        const volatile unsigned long long* vrow =
            (const volatile unsigned long long*)g_row;

        int tgt[NSPEC];
        bool eq[NSPEC];
        int cum = 0;
#pragma unroll
        for (int s = 0; s < NSPEC; ++s) {
            unsigned long long km = vrow[b * NSPEC + s];
            tgt[s] = (int)(0xFFFFFFFFu - (unsigned)(km & 0xFFFFFFFFull));
            long long dv = is64 ? draft64[b * NSPEC + s]
                                : (long long)draft32[b * NSPEC + s];
            cum += (dv == (long long)tgt[s]) ? 1 : 0;
            eq[s] = ((cum - 1) == s);              // drafts 0..s all matched
        }

        int sum_eq = 0;
#pragma unroll
        for (int s = 0; s < NSPEC; ++s) sum_eq += eq[s] ? 1 : 0;
        const int num_rejected = NSPEC - sum_eq;

        int first_diff = 0;                        // jnp.argmin: 1st False else 0
        bool any_false = false;
#pragma unroll
        for (int s = 0; s < NSPEC; ++s)
            if (!any_false && !eq[s]) { first_diff = s; any_false = true; }

        float outrow[NSPEC + 1];
        int keep_count = 0;
#pragma unroll
        for (int s = 0; s < NSPEC; ++s) {
            bool keep = (s <= first_diff) || eq[s];
            outrow[s] = keep ? (float)tgt[s] : -1.0f;
            keep_count += keep ? 1 : 0;
        }
        const bool last_all = eq[NSPEC - 1];
        long long bonus = is64 ? bonus64[b] : (long long)bonus32[b];
        outrow[NSPEC] = last_all ? (float)bonus : -1.0f;
        keep_count += last_all ? 1 : 0;

        const float last_tok = outrow[keep_count - 1];

        // Flattened tuple: [64*9 tokens | 64 num_rejected | 64 last_token]
#pragma unroll
        for (int s = 0; s <= NSPEC; ++s)
            out[b * (NSPEC + 1) + s] = outrow[s];
        out[BATCH * (NSPEC + 1) + b]         = (float)num_rejected;
        out[BATCH * (NSPEC + 1) + BATCH + b] = last_tok;
    }

    __syncthreads();
    // Reset scratch for the next graph replay.
    for (int i = threadIdx.x; i < ROWS; i += NTHREADS) g_row[i] = 0ull;
    if (threadIdx.x == 0) { g_ticket = 0u; g_count = 0u; }
}

extern "C" void kernel_launch(void* const* d_in, const int* in_sizes, int n_in,
                              void* d_out, int out_size) {
    const float* logits = (const float*)d_in[0];   // [64, 8, 128000] fp32
    const void*  draft  = d_in[1];                 // [64, 8] int64 or int32
    const void*  bonus  = d_in[2];                 // [64, 1] int64 or int32
    (void)in_sizes; (void)n_in; (void)out_size;

    fused_kernel<<<NWORKERS, NTHREADS>>>(logits, draft, bonus, (float*)d_out);
}

// round 12
// speedup vs baseline: 1.0494x; 1.0494x over previous
#include <cuda_runtime.h>
#include <cstdint>

#define BATCH 64
#define NSPEC 8
#define VOCAB 128000
#define ROWS (BATCH * NSPEC)               // 512
#define VEC_PER_ROW (VOCAB / 4)            // 32000
#define UNITS_PER_ROW 25
#define VEC_PER_UNIT (VEC_PER_ROW / UNITS_PER_ROW)   // 1280
#define NUNITS (ROWS * UNITS_PER_ROW)      // 12800 CTAs
#define NTHREADS 128
#define VPT 10                             // float4 per thread (1280/128)

// Scratch (device globals, allocation-free; zero at load, re-zeroed by the
// epilogue every call -> graph-replay deterministic).
__device__ unsigned long long g_row[ROWS]; // packed (ford(val)<<32 | ~idx) max
__device__ unsigned g_count;

// Monotone order-preserving fp32 -> u32 (no NaNs in input).
__device__ __forceinline__ unsigned ford(float f) {
    unsigned u = __float_as_uint(f);
    return u ^ ((unsigned)((int)u >> 31) | 0x80000000u);
}

__device__ __forceinline__ float max4(float4 v) {
    return fmaxf(fmaxf(v.x, v.y), fmaxf(v.z, v.w));
}

// One CTA = one 1280-float4 unit. Hardware CLC distributor provides the
// load balancing (12800 CTAs stream through 148 SMs x 8 slots); no software
// ticketing, no in-loop syncs.
__global__ void __launch_bounds__(NTHREADS, 8)
fused_kernel(const float* __restrict__ logits,
             const void* __restrict__ draft_raw,
             const void* __restrict__ bonus_raw,
             float* __restrict__ out) {
    const float4* __restrict__ vec = reinterpret_cast<const float4*>(logits);
    const int unit = blockIdx.x;
    const int row = unit / UNITS_PER_ROW;
    const int seg = unit - row * UNITS_PER_ROW;
    const int k0 = seg * VEC_PER_UNIT + threadIdx.x;     // vec idx within row
    const float4* __restrict__ pr = vec + (size_t)row * VEC_PER_ROW + k0;

    // Front-batched loads (10 LDG.128 in flight per thread).
    float4 v[VPT];
#pragma unroll
    for (int j = 0; j < VPT; ++j) v[j] = __ldcs(pr + j * NTHREADS);

    float m[VPT];
#pragma unroll
    for (int j = 0; j < VPT; ++j) m[j] = max4(v[j]);
    float bm = m[0];
#pragma unroll
    for (int j = 1; j < VPT; ++j) bm = fmaxf(bm, m[j]);

    // Earliest winning vector (jnp first-index tie-break), register-resident.
    int jbest = 0;
    bool f = false;
#pragma unroll
    for (int j = 0; j < VPT; ++j)
        if (!f && m[j] == bm) { jbest = j; f = true; }
    float4 vb = v[0];
#pragma unroll
    for (int j = 1; j < VPT; ++j)
        if (j == jbest) vb = v[j];                       // predicated selects
    const int base = (k0 + jbest * NTHREADS) * 4;
    const int bidx = (vb.x == bm) ? base
                   : (vb.y == bm) ? base + 1
                   : (vb.z == bm) ? base + 2
                   : base + 3;

    // Pack (value, ~idx): u64 max == (max value, then smallest row index).
    unsigned long long key =
        ((unsigned long long)ford(bm) << 32) |
        (unsigned long long)(0xFFFFFFFFu - (unsigned)bidx);

#pragma unroll
    for (int off = 16; off > 0; off >>= 1) {
        unsigned long long o = __shfl_down_sync(0xFFFFFFFFu, key, off);
        key = (o > key) ? o : key;
    }
    if ((threadIdx.x & 31) == 0)
        atomicMax(&g_row[row], key);          // 4 atomics/CTA, 512 addresses

    // ---- last-CTA-done handshake ----
    __shared__ int s_last;
    __shared__ int s_not64;
    if (threadIdx.x == 0) {
        __threadfence();
        unsigned c = atomicAdd(&g_count, 1u);
        s_last = (c == (unsigned)(gridDim.x - 1));
        s_not64 = 0;
    }
    __syncthreads();
    if (!s_last) return;
    __threadfence();                          // acquire all atomicMax results

    // ---- rejection-sampling epilogue ----
    // Runtime input dtype detect: first 2048 B of draft exist under either
    // dtype; int64 => every high word is 0 (tokens < 128000).
    const unsigned long long* d64chk = (const unsigned long long*)draft_raw;
    for (int j = threadIdx.x; j < 256; j += NTHREADS)
        if (d64chk[j] >> 32) atomicOr(&s_not64, 1);
    __syncthreads();
    const bool is64 = (s_not64 == 0);

    const int b = threadIdx.x;
    if (b < BATCH) {
        const long long* draft64 = (const long long*)draft_raw;
        const int*       draft32 = (const int*)draft_raw;
        const long long* bonus64 = (const long long*)bonus_raw;
        const int*       bonus32 = (const int*)bonus_raw;
        const volatile unsigned long long* vrow =
            (const volatile unsigned long long*)g_row;

        int tgt[NSPEC];
        bool eq[NSPEC];
        int cum = 0;
#pragma unroll
        for (int s = 0; s < NSPEC; ++s) {
            unsigned long long km = vrow[b * NSPEC + s];
            tgt[s] = (int)(0xFFFFFFFFu - (unsigned)(km & 0xFFFFFFFFull));
            long long dv = is64 ? draft64[b * NSPEC + s]
                                : (long long)draft32[b * NSPEC + s];
            cum += (dv == (long long)tgt[s]) ? 1 : 0;
            eq[s] = ((cum - 1) == s);         // drafts 0..s all matched
        }

        int sum_eq = 0;
#pragma unroll
        for (int s = 0; s < NSPEC; ++s) sum_eq += eq[s] ? 1 : 0;
        const int num_rejected = NSPEC - sum_eq;

        int first_diff = 0;                   // jnp.argmin: first False else 0
        bool any_false = false;
#pragma unroll
        for (int s = 0; s < NSPEC; ++s)
            if (!any_false && !eq[s]) { first_diff = s; any_false = true; }

        float outrow[NSPEC + 1];
        int keep_count = 0;
#pragma unroll
        for (int s = 0; s < NSPEC; ++s) {
            bool keep = (s <= first_diff) || eq[s];
            outrow[s] = keep ? (float)tgt[s] : -1.0f;
            keep_count += keep ? 1 : 0;
        }
        const bool last_all = eq[NSPEC - 1];
        long long bonus = is64 ? bonus64[b] : (long long)bonus32[b];
        outrow[NSPEC] = last_all ? (float)bonus : -1.0f;
        keep_count += last_all ? 1 : 0;

        const float last_tok = outrow[keep_count - 1];

        // Flattened tuple: [64*9 tokens | 64 num_rejected | 64 last_token]
#pragma unroll
        for (int s = 0; s <= NSPEC; ++s)
            out[b * (NSPEC + 1) + s] = outrow[s];
        out[BATCH * (NSPEC + 1) + b]         = (float)num_rejected;
        out[BATCH * (NSPEC + 1) + BATCH + b] = last_tok;
    }

    __syncthreads();
    // Reset scratch for the next graph replay.
    for (int i = threadIdx.x; i < ROWS; i += NTHREADS) g_row[i] = 0ull;
    if (threadIdx.x == 0) g_count = 0u;
}

extern "C" void kernel_launch(void* const* d_in, const int* in_sizes, int n_in,
                              void* d_out, int out_size) {
    const float* logits = (const float*)d_in[0];   // [64, 8, 128000] fp32
    const void*  draft  = d_in[1];                 // [64, 8] int64 or int32
    const void*  bonus  = d_in[2];                 // [64, 1] int64 or int32
    (void)in_sizes; (void)n_in; (void)out_size;

    fused_kernel<<<NUNITS, NTHREADS>>>(logits, draft, bonus, (float*)d_out);
}